// round 15
// baseline (speedup 1.0000x reference)
#include <cuda_runtime.h>
#include <cuda_fp16.h>
#include <cstdint>
#include <math.h>

// Problem constants
#define B_   2
#define H_   64
#define W_   64
#define HW_  4096
#define M_   8192          // B*HW
#define C1_  768
#define C2_  256
#define K1_  6912          // C1*9
#define K2_  2304          // C2*9
#define OC_  256

// ---------------------------------------------------------------------------
// Static scratch  (K dimension ordered kk = k*C + c, kernel-position-major)
// ---------------------------------------------------------------------------
__device__ __half g_A[K1_ * M_];                 // gathered A[pix][kk], fp16
__device__ __half g_X[C1_ * M_];                 // source transposed [pix][c], fp16
__device__ float g_om[B_ * 27 * HW_];
__device__ __half g_W1[OC_ * K1_];
__device__ __half g_WO1[32 * K1_];
__device__ __half g_W2[OC_ * K2_];
__device__ __half g_WO2[32 * K2_];

// ---------------------------------------------------------------------------
// PTX helpers (sm_80-era, safe on family target sm_103)
// ---------------------------------------------------------------------------
__device__ __forceinline__ uint32_t smem_u32(const void* p) {
    uint32_t a;
    asm("{ .reg .u64 t; cvta.to.shared.u64 t, %1; cvt.u32.u64 %0, t; }"
        : "=r"(a) : "l"(p));
    return a;
}
__device__ __forceinline__ void ldsm_x4(uint32_t* r, uint32_t addr) {
    asm volatile("ldmatrix.sync.aligned.m8n8.x4.shared.b16 {%0,%1,%2,%3}, [%4];"
                 : "=r"(r[0]), "=r"(r[1]), "=r"(r[2]), "=r"(r[3]) : "r"(addr));
}
__device__ __forceinline__ void mma_fp16(float* c, const uint32_t* a, const uint32_t* b) {
    asm volatile(
        "mma.sync.aligned.m16n8k16.row.col.f32.f16.f16.f32 "
        "{%0,%1,%2,%3}, {%4,%5,%6,%7}, {%8,%9}, {%0,%1,%2,%3};"
        : "+f"(c[0]), "+f"(c[1]), "+f"(c[2]), "+f"(c[3])
        : "r"(a[0]), "r"(a[1]), "r"(a[2]), "r"(a[3]), "r"(b[0]), "r"(b[1]));
}
#define CP_ASYNC16(dst, src) \
    asm volatile("cp.async.cg.shared.global [%0], [%1], 16;" :: "r"(dst), "l"(src))
#define CP_ASYNC16Z(dst, src, sz) \
    asm volatile("cp.async.cg.shared.global [%0], [%1], 16, %2;" \
        :: "r"(dst), "l"(src), "r"(sz))
#define CP_COMMIT() asm volatile("cp.async.commit_group;")
#define CP_WAIT(n)  asm volatile("cp.async.wait_group %0;" :: "n"(n))

__device__ __forceinline__ uint32_t f2h2(float a, float b) {
    __half2 t = __floats2half2_rn(a, b);
    return *reinterpret_cast<uint32_t*>(&t);
}

// ---------------------------------------------------------------------------
// Source transpose + fp16 convert (layer 1 only): g_X[pix][c] = src[c][pix]
// ---------------------------------------------------------------------------
__global__ void xpose_kernel(const float* __restrict__ in0,
                             const float* __restrict__ in1,
                             const float* __restrict__ in2,
                             int C) {
    __shared__ float t[32][33];
    const int m0 = blockIdx.x * 32;
    const int c0 = blockIdx.y * 32;
    const int tx = threadIdx.x & 31;
    const int ty = threadIdx.x >> 5;

    const int pix = m0 + tx;
    const int b = pix >> 12, hw = pix & 4095;

    #pragma unroll
    for (int j = 0; j < 4; j++) {
        int c = c0 + ty + j * 8;
        const float* src = (c < 256) ? in0 : ((c < 512) ? in1 : in2);
        t[ty + j * 8][tx] = src[((b << 8) + (c & 255)) * HW_ + hw];
    }
    __syncthreads();
    #pragma unroll
    for (int j = 0; j < 4; j++) {
        int r = ty + j * 8;
        uint32_t o = (uint32_t)(m0 + r) * C + c0 + tx;
        g_X[o] = __float2half(t[tx][r]);
    }
}

// ---------------------------------------------------------------------------
// Coalesced deform-gather, half2 arithmetic, 8 channels per lane (uint4).
// ---------------------------------------------------------------------------
template<int C, int K>
__global__ __launch_bounds__(256)
void gather_kernel() {
    const int hb = blockIdx.x;
    const int h  = hb & 63;
    const int bk = hb >> 6;
    const int k  = bk % 9;
    const int b  = bk / 9;
    const uint32_t cg8 = (threadIdx.x & 31) * 8;
    const int wq  = threadIdx.x >> 5;    // 0..7
    const int ky = k / 3 - 1, kx = k % 3 - 1;

    #pragma unroll 2
    for (int it = 0; it < 8; it++) {
        const int w = wq * 8 + it;
        const int ombase = (b * 27) * HW_ + h * 64 + w;
        const float dy = g_om[ombase + (2 * k) * HW_];
        const float dx = g_om[ombase + (2 * k + 1) * HW_];
        float mk = g_om[ombase + (18 + k) * HW_];
        mk = 1.0f / (1.0f + __expf(-mk));

        const float ys = dy + (float)(h + ky);
        const float xs = dx + (float)(w + kx);
        const float y0f = floorf(ys), x0f = floorf(xs);
        const float wy = ys - y0f, wx = xs - x0f;
        const int y0 = (int)y0f, x0 = (int)x0f;
        const int y1 = y0 + 1,  x1 = x0 + 1;
        const float vy0 = (y0 >= 0 && y0 < 64) ? 1.f : 0.f;
        const float vy1 = (y1 >= 0 && y1 < 64) ? 1.f : 0.f;
        const float vx0 = (x0 >= 0 && x0 < 64) ? 1.f : 0.f;
        const float vx1 = (x1 >= 0 && x1 < 64) ? 1.f : 0.f;
        const int y0c = min(max(y0, 0), 63), y1c = min(max(y1, 0), 63);
        const int x0c = min(max(x0, 0), 63), x1c = min(max(x1, 0), 63);
        const float w00 = (1.f - wy) * (1.f - wx) * vy0 * vx0 * mk;
        const float w01 = (1.f - wy) * wx * vy0 * vx1 * mk;
        const float w10 = wy * (1.f - wx) * vy1 * vx0 * mk;
        const float w11 = wy * wx * vy1 * vx1 * mk;
        const __half2 W00 = __float2half2_rn(w00);
        const __half2 W01 = __float2half2_rn(w01);
        const __half2 W10 = __float2half2_rn(w10);
        const __half2 W11 = __float2half2_rn(w11);
        const uint32_t bb = (uint32_t)(b * 4096);
        uint32_t o00 = (bb + y0c * 64 + x0c) * (uint32_t)C + cg8;
        uint32_t o01 = (bb + y0c * 64 + x1c) * (uint32_t)C + cg8;
        uint32_t o10 = (bb + y1c * 64 + x0c) * (uint32_t)C + cg8;
        uint32_t o11 = (bb + y1c * 64 + x1c) * (uint32_t)C + cg8;
        uint32_t oo  = (bb + h * 64 + w) * (uint32_t)K + (uint32_t)(k * C) + cg8;

        #pragma unroll
        for (int c0 = 0; c0 < C; c0 += 256) {
            __half2 r00[4], r01[4], r10[4], r11[4];
            *(uint4*)r00 = *(const uint4*)(g_X + o00);
            *(uint4*)r01 = *(const uint4*)(g_X + o01);
            *(uint4*)r10 = *(const uint4*)(g_X + o10);
            *(uint4*)r11 = *(const uint4*)(g_X + o11);
            __half2 ov[4];
            #pragma unroll
            for (int j = 0; j < 4; j++) {
                __half2 acc = __hmul2(W00, r00[j]);
                acc = __hfma2(W01, r01[j], acc);
                acc = __hfma2(W10, r10[j], acc);
                acc = __hfma2(W11, r11[j], acc);
                ov[j] = acc;
            }
            *(uint4*)(g_A + oo) = *(uint4*)ov;
            o00 += 256; o01 += 256; o10 += 256; o11 += 256; oo += 256;
        }
    }
}

// ---------------------------------------------------------------------------
// Coalesced weight convert: one block per (array, n, 32-channel group).
// Reads 288 contiguous floats, SMEM transpose, writes 9 x 64B half chunks.
// dst[n][k*C+c] = fp16(w[n][c][k])
// ---------------------------------------------------------------------------
#define NB1O (32 * (C1_ / 32))   // 768
#define NB1  (256 * (C1_ / 32))  // 6144
#define NB2O (32 * (C2_ / 32))   // 256
#define NB2  (256 * (C2_ / 32))  // 2048
__global__ __launch_bounds__(288)
void wconvert_all_kernel(const float* __restrict__ w_off1,
                         const float* __restrict__ w1,
                         const float* __restrict__ w_off2,
                         const float* __restrict__ w2) {
    __shared__ __half s[288];
    int bid = blockIdx.x;
    const float* w;
    __half* dst;
    int C, K, Nsrc;
    if (bid < NB1O) {
        w = w_off1; dst = g_WO1; C = C1_; K = K1_; Nsrc = 27;
    } else if (bid < NB1O + NB1) {
        bid -= NB1O;
        w = w1; dst = g_W1; C = C1_; K = K1_; Nsrc = 256;
    } else if (bid < NB1O + NB1 + NB2O) {
        bid -= NB1O + NB1;
        w = w_off2; dst = g_WO2; C = C2_; K = K2_; Nsrc = 27;
    } else {
        bid -= NB1O + NB1 + NB2O;
        w = w2; dst = g_W2; C = C2_; K = K2_; Nsrc = 256;
    }
    const int ncb = C / 32;
    const int n  = bid / ncb;
    const int cb = bid - n * ncb;
    const int t  = threadIdx.x;

    float v = (n < Nsrc) ? w[(size_t)n * K + cb * 288 + t] : 0.f;
    s[t] = __float2half(v);
    __syncthreads();
    // t -> (k = t/32, c = t%32); source smem idx = c*9 + k
    int k = t >> 5, c = t & 31;
    dst[(size_t)n * K + k * C + cb * 32 + c] = s[c * 9 + k];
}

// ---------------------------------------------------------------------------
// mma.sync fp16 GEMM, BK=64, 4-stage cp.async pipeline + register-fragment
// double buffering. SMEM row stride 144 B -> conflict-free ldmatrix.
// SHIFTED=0: A from g_A. SHIFTED=1: implicit im2col from g_X.
// MODE 0: g_om = D + bias (n<27)
// MODE 1: g_X[pix][n] = fp16(bn_relu(D))            (layer-1 output, pix-major)
// MODE 2: out = leaky(resid + gamma*bn_relu(D))     (NCHW)
// ---------------------------------------------------------------------------
template<int BM, int K, int NT, int WM, int WN, int MODE, int WSEL, int SHIFTED, int SWAP>
__global__ __launch_bounds__(256, 2)
void mm_gemm_kernel(const float* __restrict__ bias,
                    float* __restrict__ outp,
                    const float* __restrict__ bng, const float* __restrict__ bnb,
                    const float* __restrict__ bnm, const float* __restrict__ bnv,
                    const float* __restrict__ resid, const float* __restrict__ gamma) {
    extern __shared__ __align__(16) char dsm[];
    constexpr int STR  = 144;                    // bytes per 64-half row
    constexpr int offB = BM * STR;
    constexpr int S    = (BM + NT) * STR;        // bytes per stage
    constexpr int C    = K / 9;
    static_assert(C % 64 == 0, "BK=64 chunk must not straddle kernel positions");
    const uint32_t ub = smem_u32(dsm);

    constexpr int MI = WM / 16;
    constexpr int NJ = WN / 8;
    constexpr int NJH = NJ / 2;
    constexpr int MWn = BM / WM;
    constexpr int NWn = NT / WN;
    static_assert(MWn * NWn == 8, "warp grid must be 8 warps");

    const int tid = threadIdx.x;
    const int wrp = tid >> 5;
    const int l   = tid & 31;
    const int warp_m = (wrp % MWn) * WM;
    const int warp_n = (wrp / MWn) * WN;
    const int m0 = (SWAP ? blockIdx.y : blockIdx.x) * BM;
    const int n0 = (SWAP ? blockIdx.x : blockIdx.y) * NT;

    const __half* gW;
    if (WSEL == 0)      gW = g_WO1;
    else if (WSEL == 1) gW = g_W1;
    else if (WSEL == 2) gW = g_WO2;
    else                gW = g_W2;

    float acc[MI][NJ][4];
    #pragma unroll
    for (int i = 0; i < MI; i++)
        #pragma unroll
        for (int j = 0; j < NJ; j++)
            #pragma unroll
            for (int q = 0; q < 4; q++) acc[i][j][q] = 0.f;

    const uint32_t a_row  = (uint32_t)(l & 15);
    const uint32_t a_koff = (uint32_t)((l >> 4) * 16);
    const uint32_t b_row  = (uint32_t)((l & 7) + ((l >> 4) << 3));
    const uint32_t b_koff = (uint32_t)(((l >> 3) & 1) * 16);

    auto load_tiles = [&](int ch, int buf) {
        const int k0 = ch * 64;
        const uint32_t bb = ub + (uint32_t)buf * S;
        if (SHIFTED) {
            const int kpos = k0 / C;
            const int c0   = k0 - kpos * C;
            const int ky = kpos / 3 - 1, kx = kpos % 3 - 1;
            const int shift = ky * 64 + kx;
            #pragma unroll
            for (int itr = 0; itr < BM * 8 / 256; itr++) {
                int i = tid + itr * 256;
                int r = i >> 3, seg = i & 7;
                int pix = m0 + r;
                int h = (pix >> 6) & 63, w = pix & 63;
                int y = h + ky, x = w + kx;
                bool ok = (y >= 0 && y < 64 && x >= 0 && x < 64);
                int srcpix = ok ? (pix + shift) : 0;
                int sz = ok ? 16 : 0;
                uint32_t go = (uint32_t)srcpix * C + c0 + seg * 8;
                uint32_t so = (uint32_t)(r * STR + seg * 16);
                CP_ASYNC16Z(bb + so, g_X + go, sz);
            }
        } else {
            #pragma unroll
            for (int itr = 0; itr < BM * 8 / 256; itr++) {
                int i = tid + itr * 256;
                int r = i >> 3, seg = i & 7;
                uint32_t go = (uint32_t)(m0 + r) * K + k0 + seg * 8;
                uint32_t so = (uint32_t)(r * STR + seg * 16);
                CP_ASYNC16(bb + so, g_A + go);
            }
        }
        if (NT * 8 >= 256) {
            #pragma unroll
            for (int itr = 0; itr < NT * 8 / 256; itr++) {
                int i = tid + itr * 256;
                int r = i >> 3, seg = i & 7;
                uint32_t go = (uint32_t)(n0 + r) * K + k0 + seg * 8;
                uint32_t so = (uint32_t)(r * STR + seg * 16);
                CP_ASYNC16(bb + offB + so, gW + go);
            }
        } else {
            if (tid < NT * 8) {
                int r = tid >> 3, seg = tid & 7;
                uint32_t go = (uint32_t)(n0 + r) * K + k0 + seg * 8;
                uint32_t so = (uint32_t)(r * STR + seg * 16);
                CP_ASYNC16(bb + offB + so, gW + go);
            }
        }
    };

    constexpr int NCH = K / 64;
    constexpr int NSTG = 4;
    load_tiles(0, 0);
    CP_COMMIT();
    if (NCH > 1) { load_tiles(1, 1); CP_COMMIT(); }
    if (NCH > 2) { load_tiles(2, 2); CP_COMMIT(); }

    int buf = 0;
    for (int ch = 0; ch < NCH; ch++) {
        if (ch + 3 < NCH) {
            load_tiles(ch + 3, (buf + 3) % NSTG);
            CP_COMMIT();
            CP_WAIT(3);
        } else if (ch + 2 < NCH) {
            CP_WAIT(2);
        } else if (ch + 1 < NCH) {
            CP_WAIT(1);
        } else {
            CP_WAIT(0);
        }
        __syncthreads();

        const uint32_t bb = ub + (uint32_t)buf * S;
        // register-fragment double buffering across the 4 ks steps
        uint32_t aF[2][MI][4], bF[2][NJH][4];
        auto load_frag = [&](int ks, int pb) {
            #pragma unroll
            for (int i = 0; i < MI; i++) {
                uint32_t off = bb + (uint32_t)((warp_m + i * 16 + a_row) * STR + ks * 32) + a_koff;
                ldsm_x4(aF[pb][i], off);
            }
            #pragma unroll
            for (int jj = 0; jj < NJH; jj++) {
                uint32_t off = bb + offB +
                    (uint32_t)((warp_n + jj * 16 + b_row) * STR + ks * 32) + b_koff;
                ldsm_x4(bF[pb][jj], off);
            }
        };
        load_frag(0, 0);
        #pragma unroll
        for (int ks = 0; ks < 4; ks++) {
            if (ks < 3) load_frag(ks + 1, (ks + 1) & 1);
            const int pb = ks & 1;
            #pragma unroll
            for (int jj = 0; jj < NJH; jj++) {
                #pragma unroll
                for (int i = 0; i < MI; i++) {
                    mma_fp16(acc[i][jj * 2],     aF[pb][i], bF[pb][jj]);
                    mma_fp16(acc[i][jj * 2 + 1], aF[pb][i], bF[pb][jj] + 2);
                }
            }
        }
        __syncthreads();
        buf = (buf + 1) % NSTG;
    }

    // Epilogue
    if (MODE == 1) {
        #pragma unroll
        for (int i = 0; i < MI; i++) {
            #pragma unroll
            for (int j = 0; j < NJ; j++) {
                #pragma unroll
                for (int qh = 0; qh < 2; qh++) {
                    int m = m0 + warp_m + i * 16 + (l >> 2) + qh * 8;
                    int n = n0 + warp_n + j * 8 + (l & 3) * 2;
                    float v0 = acc[i][j][qh * 2];
                    float v1 = acc[i][j][qh * 2 + 1];
                    float sc0 = bng[n] * rsqrtf(bnv[n] + 1e-5f);
                    float sh0 = bnb[n] - bnm[n] * sc0;
                    float sc1 = bng[n + 1] * rsqrtf(bnv[n + 1] + 1e-5f);
                    float sh1 = bnb[n + 1] - bnm[n + 1] * sc1;
                    float t0 = fmaxf(v0 * sc0 + sh0, 0.f);
                    float t1 = fmaxf(v1 * sc1 + sh1, 0.f);
                    uint32_t o = (uint32_t)m * 256 + n;
                    *(uint32_t*)(g_X + o) = f2h2(t0, t1);
                }
            }
        }
    } else {
        const float gam = (MODE == 2) ? gamma[0] : 0.f;
        #pragma unroll
        for (int i = 0; i < MI; i++) {
            #pragma unroll
            for (int j = 0; j < NJ; j++) {
                #pragma unroll
                for (int q = 0; q < 4; q++) {
                    int m = m0 + warp_m + i * 16 + (l >> 2) + ((q >> 1) << 3);
                    int n = n0 + warp_n + j * 8 + (l & 3) * 2 + (q & 1);
                    int b  = m >> 12;
                    int hw = m & 4095;
                    float v = acc[i][j][q];
                    if (MODE == 0) {
                        if (n < 27) g_om[(b * 27 + n) * HW_ + hw] = v + bias[n];
                    } else {
                        float scale = bng[n] * rsqrtf(bnv[n] + 1e-5f);
                        float shift = bnb[n] - bnm[n] * scale;
                        float t = fmaxf(v * scale + shift, 0.f);
                        int oidx = (b * OC_ + n) * HW_ + hw;
                        float o = resid[oidx] + gam * t;
                        outp[oidx] = (o >= 0.f) ? o : 0.01f * o;
                    }
                }
            }
        }
    }
}

// ---------------------------------------------------------------------------
extern "C" void kernel_launch(void* const* d_in, const int* in_sizes, int n_in,
                              void* d_out, int out_size) {
    const float* x      = (const float*)d_in[0];
    const float* msg1   = (const float*)d_in[1];
    const float* msg2   = (const float*)d_in[2];
    const float* w_off1 = (const float*)d_in[3];
    const float* b_off1 = (const float*)d_in[4];
    const float* w1     = (const float*)d_in[5];
    const float* bn1g   = (const float*)d_in[6];
    const float* bn1b   = (const float*)d_in[7];
    const float* bn1m   = (const float*)d_in[8];
    const float* bn1v   = (const float*)d_in[9];
    const float* w_off2 = (const float*)d_in[10];
    const float* b_off2 = (const float*)d_in[11];
    const float* w2     = (const float*)d_in[12];
    const float* bn2g   = (const float*)d_in[13];
    const float* bn2b   = (const float*)d_in[14];
    const float* bn2m   = (const float*)d_in[15];
    const float* bn2v   = (const float*)d_in[16];
    const float* gamma  = (const float*)d_in[17];
    float* out = (float*)d_out;
    const float* nul = nullptr;

    constexpr int SM_MAIN = 4 * (64 + 128) * 144;  // 110592
    constexpr int SM_OFF  = 4 * (64 + 32) * 144;   // 55296
    cudaFuncSetAttribute(mm_gemm_kernel<64, K1_, 32, 16, 16, 0, 0, 1, 0>,
                         cudaFuncAttributeMaxDynamicSharedMemorySize, SM_OFF);
    cudaFuncSetAttribute(mm_gemm_kernel<64, K1_, 128, 32, 32, 1, 1, 0, 1>,
                         cudaFuncAttributeMaxDynamicSharedMemorySize, SM_MAIN);
    cudaFuncSetAttribute(mm_gemm_kernel<64, K2_, 32, 16, 16, 0, 2, 1, 0>,
                         cudaFuncAttributeMaxDynamicSharedMemorySize, SM_OFF);
    cudaFuncSetAttribute(mm_gemm_kernel<64, K2_, 128, 32, 32, 2, 3, 0, 1>,
                         cudaFuncAttributeMaxDynamicSharedMemorySize, SM_MAIN);

    // All weight conversions, one launch (coalesced)
    wconvert_all_kernel<<<NB1O + NB1 + NB2O + NB2, 288>>>(w_off1, w1, w_off2, w2);

    // ---- Layer 1 ----
    xpose_kernel<<<dim3(M_ / 32, C1_ / 32), 256>>>(x, msg1, msg2, C1_);
    mm_gemm_kernel<64, K1_, 32, 16, 16, 0, 0, 1, 0><<<dim3(M_ / 64, 1), 256, SM_OFF>>>(
        b_off1, nullptr, nul, nul, nul, nul, nul, nul);
    gather_kernel<C1_, K1_><<<B_ * 9 * H_, 256>>>();
    mm_gemm_kernel<64, K1_, 128, 32, 32, 1, 1, 0, 1><<<dim3(OC_ / 128, M_ / 64), 256, SM_MAIN>>>(
        nul, nullptr, bn1g, bn1b, bn1m, bn1v, nul, nul);

    // ---- Layer 2 ----  (X holds layer-1 output, pix-major C=256)
    mm_gemm_kernel<64, K2_, 32, 16, 16, 0, 2, 1, 0><<<dim3(M_ / 64, 1), 256, SM_OFF>>>(
        b_off2, nullptr, nul, nul, nul, nul, nul, nul);
    gather_kernel<C2_, K2_><<<B_ * 9 * H_, 256>>>();
    mm_gemm_kernel<64, K2_, 128, 32, 32, 2, 3, 0, 1><<<dim3(OC_ / 128, M_ / 64), 256, SM_MAIN>>>(
        nul, out, bn2g, bn2b, bn2m, bn2v, x, gamma);
}

// round 16
// speedup vs baseline: 1.0937x; 1.0937x over previous
#include <cuda_runtime.h>
#include <cuda_fp16.h>
#include <cstdint>
#include <math.h>

// Problem constants
#define B_   2
#define H_   64
#define W_   64
#define HW_  4096
#define M_   8192          // B*HW
#define C1_  768
#define C2_  256
#define K1_  6912          // C1*9
#define K2_  2304          // C2*9
#define OC_  256

// ---------------------------------------------------------------------------
// Static scratch  (K dimension ordered kk = k*C + c, kernel-position-major)
// ---------------------------------------------------------------------------
__device__ __half g_A[K1_ * M_];                 // gathered A[pix][kk], fp16
__device__ __half g_X[C1_ * M_];                 // source transposed [pix][c], fp16
__device__ float g_om[B_ * 27 * HW_];
__device__ __half g_W1[OC_ * K1_];
__device__ __half g_WO1[32 * K1_];
__device__ __half g_W2[OC_ * K2_];
__device__ __half g_WO2[32 * K2_];

// ---------------------------------------------------------------------------
// PTX helpers (sm_80-era, safe on family target sm_103)
// ---------------------------------------------------------------------------
__device__ __forceinline__ uint32_t smem_u32(const void* p) {
    uint32_t a;
    asm("{ .reg .u64 t; cvta.to.shared.u64 t, %1; cvt.u32.u64 %0, t; }"
        : "=r"(a) : "l"(p));
    return a;
}
__device__ __forceinline__ void ldsm_x4(uint32_t* r, uint32_t addr) {
    asm volatile("ldmatrix.sync.aligned.m8n8.x4.shared.b16 {%0,%1,%2,%3}, [%4];"
                 : "=r"(r[0]), "=r"(r[1]), "=r"(r[2]), "=r"(r[3]) : "r"(addr));
}
__device__ __forceinline__ void mma_fp16(float* c, const uint32_t* a, const uint32_t* b) {
    asm volatile(
        "mma.sync.aligned.m16n8k16.row.col.f32.f16.f16.f32 "
        "{%0,%1,%2,%3}, {%4,%5,%6,%7}, {%8,%9}, {%0,%1,%2,%3};"
        : "+f"(c[0]), "+f"(c[1]), "+f"(c[2]), "+f"(c[3])
        : "r"(a[0]), "r"(a[1]), "r"(a[2]), "r"(a[3]), "r"(b[0]), "r"(b[1]));
}
#define CP_ASYNC16(dst, src) \
    asm volatile("cp.async.cg.shared.global [%0], [%1], 16;" :: "r"(dst), "l"(src))
#define CP_ASYNC16Z(dst, src, sz) \
    asm volatile("cp.async.cg.shared.global [%0], [%1], 16, %2;" \
        :: "r"(dst), "l"(src), "r"(sz))
#define CP_COMMIT() asm volatile("cp.async.commit_group;")
#define CP_WAIT(n)  asm volatile("cp.async.wait_group %0;" :: "n"(n))

__device__ __forceinline__ uint32_t f2h2(float a, float b) {
    __half2 t = __floats2half2_rn(a, b);
    return *reinterpret_cast<uint32_t*>(&t);
}

// ---------------------------------------------------------------------------
// Source transpose + fp16 convert (layer 1 only): g_X[pix][c] = src[c][pix]
// ---------------------------------------------------------------------------
__global__ void xpose_kernel(const float* __restrict__ in0,
                             const float* __restrict__ in1,
                             const float* __restrict__ in2,
                             int C) {
    __shared__ float t[32][33];
    const int m0 = blockIdx.x * 32;
    const int c0 = blockIdx.y * 32;
    const int tx = threadIdx.x & 31;
    const int ty = threadIdx.x >> 5;

    const int pix = m0 + tx;
    const int b = pix >> 12, hw = pix & 4095;

    #pragma unroll
    for (int j = 0; j < 4; j++) {
        int c = c0 + ty + j * 8;
        const float* src = (c < 256) ? in0 : ((c < 512) ? in1 : in2);
        t[ty + j * 8][tx] = src[((b << 8) + (c & 255)) * HW_ + hw];
    }
    __syncthreads();
    #pragma unroll
    for (int j = 0; j < 4; j++) {
        int r = ty + j * 8;
        uint32_t o = (uint32_t)(m0 + r) * C + c0 + tx;
        g_X[o] = __float2half(t[tx][r]);
    }
}

// ---------------------------------------------------------------------------
// Coalesced deform-gather, half2 arithmetic, 8 channels per lane (uint4).
// ---------------------------------------------------------------------------
template<int C, int K>
__global__ __launch_bounds__(256)
void gather_kernel() {
    const int hb = blockIdx.x;
    const int h  = hb & 63;
    const int bk = hb >> 6;
    const int k  = bk % 9;
    const int b  = bk / 9;
    const uint32_t cg8 = (threadIdx.x & 31) * 8;
    const int wq  = threadIdx.x >> 5;    // 0..7
    const int ky = k / 3 - 1, kx = k % 3 - 1;

    #pragma unroll 2
    for (int it = 0; it < 8; it++) {
        const int w = wq * 8 + it;
        const int ombase = (b * 27) * HW_ + h * 64 + w;
        const float dy = g_om[ombase + (2 * k) * HW_];
        const float dx = g_om[ombase + (2 * k + 1) * HW_];
        float mk = g_om[ombase + (18 + k) * HW_];
        mk = 1.0f / (1.0f + __expf(-mk));

        const float ys = dy + (float)(h + ky);
        const float xs = dx + (float)(w + kx);
        const float y0f = floorf(ys), x0f = floorf(xs);
        const float wy = ys - y0f, wx = xs - x0f;
        const int y0 = (int)y0f, x0 = (int)x0f;
        const int y1 = y0 + 1,  x1 = x0 + 1;
        const float vy0 = (y0 >= 0 && y0 < 64) ? 1.f : 0.f;
        const float vy1 = (y1 >= 0 && y1 < 64) ? 1.f : 0.f;
        const float vx0 = (x0 >= 0 && x0 < 64) ? 1.f : 0.f;
        const float vx1 = (x1 >= 0 && x1 < 64) ? 1.f : 0.f;
        const int y0c = min(max(y0, 0), 63), y1c = min(max(y1, 0), 63);
        const int x0c = min(max(x0, 0), 63), x1c = min(max(x1, 0), 63);
        const float w00 = (1.f - wy) * (1.f - wx) * vy0 * vx0 * mk;
        const float w01 = (1.f - wy) * wx * vy0 * vx1 * mk;
        const float w10 = wy * (1.f - wx) * vy1 * vx0 * mk;
        const float w11 = wy * wx * vy1 * vx1 * mk;
        const __half2 W00 = __float2half2_rn(w00);
        const __half2 W01 = __float2half2_rn(w01);
        const __half2 W10 = __float2half2_rn(w10);
        const __half2 W11 = __float2half2_rn(w11);
        const uint32_t bb = (uint32_t)(b * 4096);
        uint32_t o00 = (bb + y0c * 64 + x0c) * (uint32_t)C + cg8;
        uint32_t o01 = (bb + y0c * 64 + x1c) * (uint32_t)C + cg8;
        uint32_t o10 = (bb + y1c * 64 + x0c) * (uint32_t)C + cg8;
        uint32_t o11 = (bb + y1c * 64 + x1c) * (uint32_t)C + cg8;
        uint32_t oo  = (bb + h * 64 + w) * (uint32_t)K + (uint32_t)(k * C) + cg8;

        #pragma unroll
        for (int c0 = 0; c0 < C; c0 += 256) {
            __half2 r00[4], r01[4], r10[4], r11[4];
            *(uint4*)r00 = *(const uint4*)(g_X + o00);
            *(uint4*)r01 = *(const uint4*)(g_X + o01);
            *(uint4*)r10 = *(const uint4*)(g_X + o10);
            *(uint4*)r11 = *(const uint4*)(g_X + o11);
            __half2 ov[4];
            #pragma unroll
            for (int j = 0; j < 4; j++) {
                __half2 acc = __hmul2(W00, r00[j]);
                acc = __hfma2(W01, r01[j], acc);
                acc = __hfma2(W10, r10[j], acc);
                acc = __hfma2(W11, r11[j], acc);
                ov[j] = acc;
            }
            *(uint4*)(g_A + oo) = *(uint4*)ov;
            o00 += 256; o01 += 256; o10 += 256; o11 += 256; oo += 256;
        }
    }
}

// ---------------------------------------------------------------------------
// Coalesced weight convert: one block per (array, n, 32-channel group).
// dst[n][k*C+c] = fp16(w[n][c][k])
// ---------------------------------------------------------------------------
#define NB1O (32 * (C1_ / 32))   // 768
#define NB1  (256 * (C1_ / 32))  // 6144
#define NB2O (32 * (C2_ / 32))   // 256
#define NB2  (256 * (C2_ / 32))  // 2048
__global__ __launch_bounds__(288)
void wconvert_all_kernel(const float* __restrict__ w_off1,
                         const float* __restrict__ w1,
                         const float* __restrict__ w_off2,
                         const float* __restrict__ w2) {
    __shared__ __half s[288];
    int bid = blockIdx.x;
    const float* w;
    __half* dst;
    int C, K, Nsrc;
    if (bid < NB1O) {
        w = w_off1; dst = g_WO1; C = C1_; K = K1_; Nsrc = 27;
    } else if (bid < NB1O + NB1) {
        bid -= NB1O;
        w = w1; dst = g_W1; C = C1_; K = K1_; Nsrc = 256;
    } else if (bid < NB1O + NB1 + NB2O) {
        bid -= NB1O + NB1;
        w = w_off2; dst = g_WO2; C = C2_; K = K2_; Nsrc = 27;
    } else {
        bid -= NB1O + NB1 + NB2O;
        w = w2; dst = g_W2; C = C2_; K = K2_; Nsrc = 256;
    }
    const int ncb = C / 32;
    const int n  = bid / ncb;
    const int cb = bid - n * ncb;
    const int t  = threadIdx.x;

    float v = (n < Nsrc) ? w[(size_t)n * K + cb * 288 + t] : 0.f;
    s[t] = __float2half(v);
    __syncthreads();
    int k = t >> 5, c = t & 31;
    dst[(size_t)n * K + k * C + cb * 32 + c] = s[c * 9 + k];
}

// ---------------------------------------------------------------------------
// mma.sync fp16 GEMM, BK=64, NSTG-stage cp.async pipeline, tile BM x NT.
// SMEM row stride 144 B -> conflict-free ldmatrix.
// SHIFTED=0: A from g_A. SHIFTED=1: implicit im2col from g_X.
// MODE 0: g_om = D + bias (n<27)
// MODE 1: g_X[pix][n] = fp16(bn_relu(D))            (layer-1 output, pix-major)
// MODE 2: out = leaky(resid + gamma*bn_relu(D))     (NCHW)
// ---------------------------------------------------------------------------
template<int BM, int K, int NT, int WM, int WN, int NSTG,
         int MODE, int WSEL, int SHIFTED, int SWAP>
__global__ __launch_bounds__(256, 2)
void mm_gemm_kernel(const float* __restrict__ bias,
                    float* __restrict__ outp,
                    const float* __restrict__ bng, const float* __restrict__ bnb,
                    const float* __restrict__ bnm, const float* __restrict__ bnv,
                    const float* __restrict__ resid, const float* __restrict__ gamma) {
    extern __shared__ __align__(16) char dsm[];
    constexpr int STR  = 144;                    // bytes per 64-half row
    constexpr int offB = BM * STR;
    constexpr int S    = (BM + NT) * STR;        // bytes per stage
    constexpr int C    = K / 9;
    static_assert(C % 64 == 0, "BK=64 chunk must not straddle kernel positions");
    const uint32_t ub = smem_u32(dsm);

    constexpr int MI = WM / 16;
    constexpr int NJ = WN / 8;
    constexpr int NJH = NJ / 2;
    constexpr int MWn = BM / WM;
    constexpr int NWn = NT / WN;
    static_assert(MWn * NWn == 8, "warp grid must be 8 warps");

    const int tid = threadIdx.x;
    const int wrp = tid >> 5;
    const int l   = tid & 31;
    const int warp_m = (wrp % MWn) * WM;
    const int warp_n = (wrp / MWn) * WN;
    const int m0 = (SWAP ? blockIdx.y : blockIdx.x) * BM;
    const int n0 = (SWAP ? blockIdx.x : blockIdx.y) * NT;

    const __half* gW;
    if (WSEL == 0)      gW = g_WO1;
    else if (WSEL == 1) gW = g_W1;
    else if (WSEL == 2) gW = g_WO2;
    else                gW = g_W2;

    float acc[MI][NJ][4];
    #pragma unroll
    for (int i = 0; i < MI; i++)
        #pragma unroll
        for (int j = 0; j < NJ; j++)
            #pragma unroll
            for (int q = 0; q < 4; q++) acc[i][j][q] = 0.f;

    const uint32_t a_row  = (uint32_t)(l & 15);
    const uint32_t a_koff = (uint32_t)((l >> 4) * 16);
    const uint32_t b_row  = (uint32_t)((l & 7) + ((l >> 4) << 3));
    const uint32_t b_koff = (uint32_t)(((l >> 3) & 1) * 16);

    auto load_tiles = [&](int ch, int buf) {
        const int k0 = ch * 64;
        const uint32_t bb = ub + (uint32_t)buf * S;
        if (SHIFTED) {
            const int kpos = k0 / C;
            const int c0   = k0 - kpos * C;
            const int ky = kpos / 3 - 1, kx = kpos % 3 - 1;
            const int shift = ky * 64 + kx;
            #pragma unroll
            for (int itr = 0; itr < BM * 8 / 256; itr++) {
                int i = tid + itr * 256;
                int r = i >> 3, seg = i & 7;
                int pix = m0 + r;
                int h = (pix >> 6) & 63, w = pix & 63;
                int y = h + ky, x = w + kx;
                bool ok = (y >= 0 && y < 64 && x >= 0 && x < 64);
                int srcpix = ok ? (pix + shift) : 0;
                int sz = ok ? 16 : 0;
                uint32_t go = (uint32_t)srcpix * C + c0 + seg * 8;
                uint32_t so = (uint32_t)(r * STR + seg * 16);
                CP_ASYNC16Z(bb + so, g_X + go, sz);
            }
        } else {
            #pragma unroll
            for (int itr = 0; itr < BM * 8 / 256; itr++) {
                int i = tid + itr * 256;
                int r = i >> 3, seg = i & 7;
                uint32_t go = (uint32_t)(m0 + r) * K + k0 + seg * 8;
                uint32_t so = (uint32_t)(r * STR + seg * 16);
                CP_ASYNC16(bb + so, g_A + go);
            }
        }
        if (NT * 8 >= 256) {
            #pragma unroll
            for (int itr = 0; itr < NT * 8 / 256; itr++) {
                int i = tid + itr * 256;
                int r = i >> 3, seg = i & 7;
                uint32_t go = (uint32_t)(n0 + r) * K + k0 + seg * 8;
                uint32_t so = (uint32_t)(r * STR + seg * 16);
                CP_ASYNC16(bb + offB + so, gW + go);
            }
        } else {
            if (tid < NT * 8) {
                int r = tid >> 3, seg = tid & 7;
                uint32_t go = (uint32_t)(n0 + r) * K + k0 + seg * 8;
                uint32_t so = (uint32_t)(r * STR + seg * 16);
                CP_ASYNC16(bb + offB + so, gW + go);
            }
        }
    };

    constexpr int NCH = K / 64;
    load_tiles(0, 0);
    CP_COMMIT();
    #pragma unroll
    for (int p = 1; p < NSTG - 1; p++) {
        if (NCH > p) { load_tiles(p, p); CP_COMMIT(); }
    }

    int buf = 0;
    for (int ch = 0; ch < NCH; ch++) {
        if (ch + NSTG - 1 < NCH) {
            load_tiles(ch + NSTG - 1, (buf + NSTG - 1) % NSTG);
            CP_COMMIT();
            CP_WAIT(NSTG - 1);
        } else {
            // drain: remaining in-flight groups = NCH-1-ch
            int rem = NCH - 1 - ch;
            if (rem >= NSTG - 1) { CP_WAIT(NSTG - 1); }
            else if (rem == 2)   { CP_WAIT(2); }
            else if (rem == 1)   { CP_WAIT(1); }
            else                 { CP_WAIT(0); }
        }
        __syncthreads();

        const uint32_t bb = ub + (uint32_t)buf * S;
        #pragma unroll
        for (int ks = 0; ks < 4; ks++) {
            uint32_t a4[MI][4], b4[NJH][4];
            #pragma unroll
            for (int i = 0; i < MI; i++) {
                uint32_t off = bb + (uint32_t)((warp_m + i * 16 + a_row) * STR + ks * 32) + a_koff;
                ldsm_x4(a4[i], off);
            }
            #pragma unroll
            for (int jj = 0; jj < NJH; jj++) {
                uint32_t off = bb + offB +
                    (uint32_t)((warp_n + jj * 16 + b_row) * STR + ks * 32) + b_koff;
                ldsm_x4(b4[jj], off);
            }
            #pragma unroll
            for (int jj = 0; jj < NJH; jj++) {
                #pragma unroll
                for (int i = 0; i < MI; i++) {
                    mma_fp16(acc[i][jj * 2],     a4[i], b4[jj]);
                    mma_fp16(acc[i][jj * 2 + 1], a4[i], b4[jj] + 2);
                }
            }
        }
        __syncthreads();
        buf = (buf + 1) % NSTG;
    }

    // Epilogue
    if (MODE == 1) {
        #pragma unroll
        for (int i = 0; i < MI; i++) {
            #pragma unroll
            for (int j = 0; j < NJ; j++) {
                #pragma unroll
                for (int qh = 0; qh < 2; qh++) {
                    int m = m0 + warp_m + i * 16 + (l >> 2) + qh * 8;
                    int n = n0 + warp_n + j * 8 + (l & 3) * 2;
                    float v0 = acc[i][j][qh * 2];
                    float v1 = acc[i][j][qh * 2 + 1];
                    float sc0 = bng[n] * rsqrtf(bnv[n] + 1e-5f);
                    float sh0 = bnb[n] - bnm[n] * sc0;
                    float sc1 = bng[n + 1] * rsqrtf(bnv[n + 1] + 1e-5f);
                    float sh1 = bnb[n + 1] - bnm[n + 1] * sc1;
                    float t0 = fmaxf(v0 * sc0 + sh0, 0.f);
                    float t1 = fmaxf(v1 * sc1 + sh1, 0.f);
                    uint32_t o = (uint32_t)m * 256 + n;
                    *(uint32_t*)(g_X + o) = f2h2(t0, t1);
                }
            }
        }
    } else {
        const float gam = (MODE == 2) ? gamma[0] : 0.f;
        #pragma unroll
        for (int i = 0; i < MI; i++) {
            #pragma unroll
            for (int j = 0; j < NJ; j++) {
                #pragma unroll
                for (int q = 0; q < 4; q++) {
                    int m = m0 + warp_m + i * 16 + (l >> 2) + ((q >> 1) << 3);
                    int n = n0 + warp_n + j * 8 + (l & 3) * 2 + (q & 1);
                    int b  = m >> 12;
                    int hw = m & 4095;
                    float v = acc[i][j][q];
                    if (MODE == 0) {
                        if (n < 27) g_om[(b * 27 + n) * HW_ + hw] = v + bias[n];
                    } else {
                        float scale = bng[n] * rsqrtf(bnv[n] + 1e-5f);
                        float shift = bnb[n] - bnm[n] * scale;
                        float t = fmaxf(v * scale + shift, 0.f);
                        int oidx = (b * OC_ + n) * HW_ + hw;
                        float o = resid[oidx] + gam * t;
                        outp[oidx] = (o >= 0.f) ? o : 0.01f * o;
                    }
                }
            }
        }
    }
}

// ---------------------------------------------------------------------------
extern "C" void kernel_launch(void* const* d_in, const int* in_sizes, int n_in,
                              void* d_out, int out_size) {
    const float* x      = (const float*)d_in[0];
    const float* msg1   = (const float*)d_in[1];
    const float* msg2   = (const float*)d_in[2];
    const float* w_off1 = (const float*)d_in[3];
    const float* b_off1 = (const float*)d_in[4];
    const float* w1     = (const float*)d_in[5];
    const float* bn1g   = (const float*)d_in[6];
    const float* bn1b   = (const float*)d_in[7];
    const float* bn1m   = (const float*)d_in[8];
    const float* bn1v   = (const float*)d_in[9];
    const float* w_off2 = (const float*)d_in[10];
    const float* b_off2 = (const float*)d_in[11];
    const float* w2     = (const float*)d_in[12];
    const float* bn2g   = (const float*)d_in[13];
    const float* bn2b   = (const float*)d_in[14];
    const float* bn2m   = (const float*)d_in[15];
    const float* bn2v   = (const float*)d_in[16];
    const float* gamma  = (const float*)d_in[17];
    float* out = (float*)d_out;
    const float* nul = nullptr;

    constexpr int SM_MAIN = 3 * (128 + 128) * 144;  // 110592
    constexpr int SM_OFF  = 4 * (64 + 32) * 144;    // 55296
    cudaFuncSetAttribute(mm_gemm_kernel<64, K1_, 32, 16, 16, 4, 0, 0, 1, 0>,
                         cudaFuncAttributeMaxDynamicSharedMemorySize, SM_OFF);
    cudaFuncSetAttribute(mm_gemm_kernel<128, K1_, 128, 32, 64, 3, 1, 1, 0, 1>,
                         cudaFuncAttributeMaxDynamicSharedMemorySize, SM_MAIN);
    cudaFuncSetAttribute(mm_gemm_kernel<64, K2_, 32, 16, 16, 4, 0, 2, 1, 0>,
                         cudaFuncAttributeMaxDynamicSharedMemorySize, SM_OFF);
    cudaFuncSetAttribute(mm_gemm_kernel<128, K2_, 128, 32, 64, 3, 2, 3, 0, 1>,
                         cudaFuncAttributeMaxDynamicSharedMemorySize, SM_MAIN);

    // All weight conversions, one launch (coalesced)
    wconvert_all_kernel<<<NB1O + NB1 + NB2O + NB2, 288>>>(w_off1, w1, w_off2, w2);

    // ---- Layer 1 ----
    xpose_kernel<<<dim3(M_ / 32, C1_ / 32), 256>>>(x, msg1, msg2, C1_);
    mm_gemm_kernel<64, K1_, 32, 16, 16, 4, 0, 0, 1, 0><<<dim3(M_ / 64, 1), 256, SM_OFF>>>(
        b_off1, nullptr, nul, nul, nul, nul, nul, nul);
    gather_kernel<C1_, K1_><<<B_ * 9 * H_, 256>>>();
    mm_gemm_kernel<128, K1_, 128, 32, 64, 3, 1, 1, 0, 1>
        <<<dim3(OC_ / 128, M_ / 128), 256, SM_MAIN>>>(
        nul, nullptr, bn1g, bn1b, bn1m, bn1v, nul, nul);

    // ---- Layer 2 ----  (X holds layer-1 output, pix-major C=256)
    mm_gemm_kernel<64, K2_, 32, 16, 16, 4, 0, 2, 1, 0><<<dim3(M_ / 64, 1), 256, SM_OFF>>>(
        b_off2, nullptr, nul, nul, nul, nul, nul, nul);
    gather_kernel<C2_, K2_><<<B_ * 9 * H_, 256>>>();
    mm_gemm_kernel<128, K2_, 128, 32, 64, 3, 2, 3, 0, 1>
        <<<dim3(OC_ / 128, M_ / 128), 256, SM_MAIN>>>(
        nul, out, bn2g, bn2b, bn2m, bn2v, x, gamma);
}